// round 5
// baseline (speedup 1.0000x reference)
#include <cuda_runtime.h>
#include <cstdint>

#define SB 8
#define SS 512
#define D1 768
#define DD 64
#define NREL 130
#define GLOB 64
#define EPSF 1e-12f

// scratch (no allocations allowed)
__device__ float g_diag2[SB * SS * DD];    // 1 MB
__device__ float g_lnrel[NREL * DD];       // 33 KB

// ---------------------------------------------------------------------------
// LN of 64-float row with a 64-thread block (2 warps)
// ---------------------------------------------------------------------------
__device__ __forceinline__ float ln64(float v, int d) {
    __shared__ float s1[2], s2[2];
    float a = v, b = v * v;
    #pragma unroll
    for (int o = 16; o; o >>= 1) {
        a += __shfl_down_sync(0xffffffffu, a, o);
        b += __shfl_down_sync(0xffffffffu, b, o);
    }
    int w = d >> 5;
    if ((d & 31) == 0) { s1[w] = a; s2[w] = b; }
    __syncthreads();
    float sum = s1[0] + s1[1];
    float sq  = s2[0] + s2[1];
    float mean = sum * (1.0f / 64.0f);
    float var  = sq * (1.0f / 64.0f) - mean * mean;
    return (v - mean) * rsqrtf(var + EPSF);
}

// 1) LN(W_rel[r]) -> g_lnrel
__global__ void k_lnrel(const float* __restrict__ W_rel) {
    int r = blockIdx.x, d = threadIdx.x;
    float v = W_rel[r * DD + d];
    g_lnrel[r * DD + d] = ln64(v, d);
}

// 2) embd0 = broadcast(LN(W_glob)) -> out0 [8,64,64]
__global__ void k_glob(const float* __restrict__ W_glob, float* __restrict__ out0) {
    int g = blockIdx.x, d = threadIdx.x;
    float v = ln64(W_glob[g * DD + d], d);
    #pragma unroll
    for (int b = 0; b < SB; b++)
        out0[(b * GLOB + g) * DD + d] = v;
}

// 3) embd1 = LN(word+type+abs) -> out1 [8,512,768]; diag2 = raw @ W_diag^T + b
__global__ void __launch_bounds__(256) k_embd1(
    const int* __restrict__ tok, const int* __restrict__ tt,
    const float* __restrict__ Ww, const float* __restrict__ Wt,
    const float* __restrict__ Wa, const float* __restrict__ Wd,
    const float* __restrict__ bdiag, float* __restrict__ out1)
{
    int row = blockIdx.x;          // b*512 + s
    int s   = row & (SS - 1);
    int t   = threadIdx.x;
    __shared__ float xs[D1];
    __shared__ float red1[8], red2[8];

    int tk = tok[row], ty = tt[row];
    float xv[3];
    float lsum = 0.f, lsq = 0.f;
    #pragma unroll
    for (int e = 0; e < 3; e++) {
        int d = t + e * 256;
        float v = Ww[(size_t)tk * D1 + d] + Wt[ty * D1 + d] + Wa[s * D1 + d];
        xs[d] = v; xv[e] = v;
        lsum += v; lsq += v * v;
    }
    #pragma unroll
    for (int o = 16; o; o >>= 1) {
        lsum += __shfl_down_sync(0xffffffffu, lsum, o);
        lsq  += __shfl_down_sync(0xffffffffu, lsq,  o);
    }
    int w = t >> 5, lane = t & 31;
    if (lane == 0) { red1[w] = lsum; red2[w] = lsq; }
    __syncthreads();                       // also publishes xs[]
    float sum = 0.f, sq = 0.f;
    #pragma unroll
    for (int i = 0; i < 8; i++) { sum += red1[i]; sq += red2[i]; }
    float mean = sum * (1.0f / D1);
    float rstd = rsqrtf(sq * (1.0f / D1) - mean * mean + EPSF);
    #pragma unroll
    for (int e = 0; e < 3; e++) {
        int d = t + e * 256;
        out1[(size_t)row * D1 + d] = (xv[e] - mean) * rstd;
    }

    // diag2[row][k] = sum_d xs[d] * W_diag[k][d] + b[k]; warp w owns k in [8w,8w+8)
    #pragma unroll
    for (int kk = 0; kk < 8; kk++) {
        int k = w * 8 + kk;
        const float* wr = Wd + (size_t)k * D1;
        float p = 0.f;
        #pragma unroll
        for (int e = 0; e < 24; e++) {
            int d = lane + e * 32;
            p += xs[d] * wr[d];            // coalesced across lanes
        }
        #pragma unroll
        for (int o = 16; o; o >>= 1) p += __shfl_down_sync(0xffffffffu, p, o);
        if (lane == 0) g_diag2[row * DD + k] = p + bdiag[k];
    }
}

// rpe index, post-mask + overrides, closed form
__device__ __forceinline__ int rel_idx(int i, int j, int tti, int ttj) {
    if (i == 0 && j >= 1) return 128;
    if (j == 0 && i >= 1) return 129;
    if (tti != ttj) return 64;
    int d = i - j;
    if (d == 0) return 0;
    return (d > 0) ? (128 - min(d, 63)) : min(-d, 63);
}

// 4) main fill: out2[b,i,j,:] = ln_rel[idx(b,i,j)]  (streaming stores)
__global__ void __launch_bounds__(256) k_fill(const int* __restrict__ tt,
                                              float* __restrict__ out2)
{
    int i = blockIdx.x, b = blockIdx.y;
    int t = threadIdx.x;
    __shared__ float4 tbl[NREL * 16];          // 33280 B
    __shared__ int    tts[SS];
    __shared__ unsigned char idxs[SS];

    const float4* src = (const float4*)g_lnrel;
    for (int g = t; g < NREL * 16; g += 256) tbl[g] = src[g];
    for (int j = t; j < SS; j += 256) tts[j] = tt[b * SS + j];
    __syncthreads();

    int tti = tts[i];
    for (int j = t; j < SS; j += 256)
        idxs[j] = (unsigned char)rel_idx(i, j, tti, tts[j]);
    __syncthreads();

    float4* dst = (float4*)out2 + (size_t)(b * SS + i) * SS * 16;
    #pragma unroll 4
    for (int g = t; g < SS * 16; g += 256) {
        int j = g >> 4, q = g & 15;
        float4 v = tbl[idxs[j] * 16 + q];
        __stcs(&dst[g], v);                    // evict-first: pure stream
    }
}

// 5) diagonal overwrite: out2[b,i,i,:] = LN(W_rel[0] + diag2[b,i])
__global__ void k_diag(const float* __restrict__ W_rel, float* __restrict__ out2) {
    int row = blockIdx.x;                      // b*512 + i
    int d = threadIdx.x;
    float v = W_rel[d] + g_diag2[row * DD + d];
    float o = ln64(v, d);
    int i = row & (SS - 1);
    out2[((size_t)row * SS + i) * DD + d] = o;
}

extern "C" void kernel_launch(void* const* d_in, const int* in_sizes, int n_in,
                              void* d_out, int out_size)
{
    const int*   tok   = (const int*)  d_in[0];
    const int*   tt    = (const int*)  d_in[1];
    const float* Ww    = (const float*)d_in[2];
    const float* Wt    = (const float*)d_in[3];
    const float* Wa    = (const float*)d_in[4];
    const float* Wrel  = (const float*)d_in[5];
    const float* Wglob = (const float*)d_in[6];
    const float* Wd    = (const float*)d_in[7];
    const float* bd    = (const float*)d_in[8];

    float* out  = (float*)d_out;
    float* out0 = out;                                   // 8*64*64      = 32768
    float* out1 = out + SB * GLOB * DD;                  // 8*512*768    = 3145728
    float* out2 = out1 + (size_t)SB * SS * D1;           // 8*512*512*64

    k_lnrel<<<NREL, DD>>>(Wrel);
    k_glob <<<GLOB, DD>>>(Wglob, out0);
    k_embd1<<<SB * SS, 256>>>(tok, tt, Ww, Wt, Wa, Wd, bd, out1);
    k_fill <<<dim3(SS, SB), 256>>>(tt, out2);
    k_diag <<<SB * SS, DD>>>(Wrel, out2);
}

// round 6
// speedup vs baseline: 1.1670x; 1.1670x over previous
#include <cuda_runtime.h>
#include <cstdint>

#define SB 8
#define SS 512
#define D1 768
#define DD 64
#define NREL 130
#define GLOB 64
#define EPSF 1e-12f

// scratch (no allocations allowed)
__device__ float g_diag2[SB * SS * DD];    // 1 MB
__device__ float g_lnrel[NREL * DD];       // 33 KB

// ---------------------------------------------------------------------------
// LN of 64-float row with a 64-thread block (2 warps)
// ---------------------------------------------------------------------------
__device__ __forceinline__ float ln64(float v, int d) {
    __shared__ float s1[2], s2[2];
    float a = v, b = v * v;
    #pragma unroll
    for (int o = 16; o; o >>= 1) {
        a += __shfl_xor_sync(0xffffffffu, a, o);
        b += __shfl_xor_sync(0xffffffffu, b, o);
    }
    int w = d >> 5;
    if ((d & 31) == 0) { s1[w] = a; s2[w] = b; }
    __syncthreads();
    float sum = s1[0] + s1[1];
    float sq  = s2[0] + s2[1];
    float mean = sum * (1.0f / 64.0f);
    float var  = sq * (1.0f / 64.0f) - mean * mean;
    return (v - mean) * rsqrtf(var + EPSF);
}

// 1+2) merged: blocks [0,NREL) do LN(W_rel[r]) -> g_lnrel;
//              blocks [NREL,NREL+GLOB) do embd0 = broadcast(LN(W_glob))
__global__ void k_small(const float* __restrict__ W_rel,
                        const float* __restrict__ W_glob,
                        float* __restrict__ out0)
{
    int r = blockIdx.x, d = threadIdx.x;
    if (r < NREL) {
        g_lnrel[r * DD + d] = ln64(W_rel[r * DD + d], d);
    } else {
        int g = r - NREL;
        float v = ln64(W_glob[g * DD + d], d);
        #pragma unroll
        for (int b = 0; b < SB; b++)
            out0[(b * GLOB + g) * DD + d] = v;
    }
}

// 3) embd1 = LN(word+type+abs) -> out1; diag2 = raw @ W_diag^T + b
//    8 rows per block: warp w owns row (base+w) for the LN phase,
//    and k-range [8w, 8w+8) over ALL 8 rows for the diag GEMM phase.
__global__ void __launch_bounds__(256) k_embd1(
    const int* __restrict__ tok, const int* __restrict__ tt,
    const float* __restrict__ Ww, const float* __restrict__ Wt,
    const float* __restrict__ Wa, const float* __restrict__ Wd,
    const float* __restrict__ bdiag, float* __restrict__ out1)
{
    const int base = blockIdx.x * 8;
    const int w = threadIdx.x >> 5, lane = threadIdx.x & 31;
    const int row = base + w;
    const int s = row & (SS - 1);

    __shared__ float4 xs4[8][D1 / 4];          // 24 KB raw rows
    float* xsf = (float*)&xs4[w][0];

    // ---- phase 1: gather + LN (warp-local) ----
    const int tk = tok[row], ty = tt[row];
    const float* __restrict__ pw = Ww + (size_t)tk * D1;
    const float* __restrict__ pt = Wt + (size_t)ty * D1;
    const float* __restrict__ pa = Wa + (size_t)s * D1;

    float v[24];
    float sum = 0.f, sq = 0.f;
    #pragma unroll
    for (int e = 0; e < 24; e++) {
        int d = lane + e * 32;
        float x = pw[d] + pt[d] + pa[d];
        v[e] = x; xsf[d] = x;
        sum += x; sq += x * x;
    }
    #pragma unroll
    for (int o = 16; o; o >>= 1) {
        sum += __shfl_xor_sync(0xffffffffu, sum, o);
        sq  += __shfl_xor_sync(0xffffffffu, sq,  o);
    }
    float mean = sum * (1.0f / D1);
    float rstd = rsqrtf(sq * (1.0f / D1) - mean * mean + EPSF);
    float* __restrict__ o1 = out1 + (size_t)row * D1;
    #pragma unroll
    for (int e = 0; e < 24; e++) {
        int d = lane + e * 32;
        o1[d] = (v[e] - mean) * rstd;
    }
    __syncthreads();                            // publish xs4

    // ---- phase 2: diag GEMM, k-blocked by 4 ----
    const float4* __restrict__ Wd4 = (const float4*)Wd;
    #pragma unroll
    for (int kg = 0; kg < 2; kg++) {
        const int k0 = w * 8 + kg * 4;
        const float4* __restrict__ w0 = Wd4 + (size_t)(k0 + 0) * (D1 / 4);
        const float4* __restrict__ w1 = Wd4 + (size_t)(k0 + 1) * (D1 / 4);
        const float4* __restrict__ w2 = Wd4 + (size_t)(k0 + 2) * (D1 / 4);
        const float4* __restrict__ w3 = Wd4 + (size_t)(k0 + 3) * (D1 / 4);

        float acc[4][8];
        #pragma unroll
        for (int c = 0; c < 4; c++)
            #pragma unroll
            for (int r = 0; r < 8; r++) acc[c][r] = 0.f;

        #pragma unroll
        for (int e = 0; e < 6; e++) {
            int dq = lane + e * 32;
            float4 a0 = w0[dq], a1 = w1[dq], a2 = w2[dq], a3 = w3[dq];
            #pragma unroll
            for (int r = 0; r < 8; r++) {
                float4 x = xs4[r][dq];
                acc[0][r] += x.x * a0.x + x.y * a0.y + x.z * a0.z + x.w * a0.w;
                acc[1][r] += x.x * a1.x + x.y * a1.y + x.z * a1.z + x.w * a1.w;
                acc[2][r] += x.x * a2.x + x.y * a2.y + x.z * a2.z + x.w * a2.w;
                acc[3][r] += x.x * a3.x + x.y * a3.y + x.z * a3.z + x.w * a3.w;
            }
        }
        #pragma unroll
        for (int c = 0; c < 4; c++)
            #pragma unroll
            for (int r = 0; r < 8; r++) {
                float p = acc[c][r];
                #pragma unroll
                for (int o = 16; o; o >>= 1)
                    p += __shfl_down_sync(0xffffffffu, p, o);
                acc[c][r] = p;
            }
        if (lane == 0) {
            #pragma unroll
            for (int c = 0; c < 4; c++) {
                float bk = bdiag[k0 + c];
                #pragma unroll
                for (int r = 0; r < 8; r++)
                    g_diag2[(size_t)(base + r) * DD + (k0 + c)] = acc[c][r] + bk;
            }
        }
    }
}

// rpe index, post-mask + overrides, closed form
__device__ __forceinline__ int rel_idx(int i, int j, int tti, int ttj) {
    if (i == 0 && j >= 1) return 128;
    if (j == 0 && i >= 1) return 129;
    if (tti != ttj) return DD;      // 64
    int d = i - j;
    if (d == 0) return 0;
    return (d > 0) ? (128 - min(d, 63)) : min(-d, 63);
}

// 4) main fill with diagonal folded in:
//    table row NREL holds LN(W_rel[0] + diag2[b,i]); idxs[i] = NREL.
__global__ void __launch_bounds__(256) k_fill(const int* __restrict__ tt,
                                              const float* __restrict__ W_rel,
                                              float* __restrict__ out2)
{
    const int i = blockIdx.x, b = blockIdx.y;
    const int t = threadIdx.x;
    __shared__ float4 tbl[(NREL + 1) * 16];        // 33536 B (incl. diag row)
    __shared__ unsigned char tts[SS];
    __shared__ unsigned char idxs[SS];
    __shared__ float ws1[2], ws2[2];

    // diag partial (threads 0..63), before block sync
    float dv = 0.f;
    if (t < DD) {
        dv = W_rel[t] + g_diag2[(size_t)(b * SS + i) * DD + t];
        float a = dv, c = dv * dv;
        #pragma unroll
        for (int o = 16; o; o >>= 1) {
            a += __shfl_xor_sync(0xffffffffu, a, o);
            c += __shfl_xor_sync(0xffffffffu, c, o);
        }
        if ((t & 31) == 0) { ws1[t >> 5] = a; ws2[t >> 5] = c; }
    }

    // cooperative loads
    const float4* src = (const float4*)g_lnrel;
    for (int g = t; g < NREL * 16; g += 256) tbl[g] = src[g];
    for (int j = t; j < SS; j += 256) tts[j] = (unsigned char)tt[b * SS + j];
    __syncthreads();

    // finish diag LN -> table row NREL
    if (t < DD) {
        float sum = ws1[0] + ws1[1];
        float sq  = ws2[0] + ws2[1];
        float mean = sum * (1.0f / 64.0f);
        float rstd = rsqrtf(sq * (1.0f / 64.0f) - mean * mean + EPSF);
        ((float*)tbl)[NREL * DD + t] = (dv - mean) * rstd;
    }

    const int tti = tts[i];
    for (int j = t; j < SS; j += 256)
        idxs[j] = (unsigned char)((j == i) ? NREL : rel_idx(i, j, tti, tts[j]));
    __syncthreads();

    float4* dst = (float4*)out2 + (size_t)(b * SS + i) * SS * 16;
    #pragma unroll 4
    for (int g = t; g < SS * 16; g += 256) {
        int j = g >> 4, q = g & 15;
        float4 vv = tbl[idxs[j] * 16 + q];
        __stcs(&dst[g], vv);                       // evict-first: pure stream
    }
}

extern "C" void kernel_launch(void* const* d_in, const int* in_sizes, int n_in,
                              void* d_out, int out_size)
{
    const int*   tok   = (const int*)  d_in[0];
    const int*   tt    = (const int*)  d_in[1];
    const float* Ww    = (const float*)d_in[2];
    const float* Wt    = (const float*)d_in[3];
    const float* Wa    = (const float*)d_in[4];
    const float* Wrel  = (const float*)d_in[5];
    const float* Wglob = (const float*)d_in[6];
    const float* Wd    = (const float*)d_in[7];
    const float* bd    = (const float*)d_in[8];

    float* out  = (float*)d_out;
    float* out0 = out;                                   // 8*64*64
    float* out1 = out + SB * GLOB * DD;                  // 8*512*768
    float* out2 = out1 + (size_t)SB * SS * D1;           // 8*512*512*64

    k_small<<<NREL + GLOB, DD>>>(Wrel, Wglob, out0);
    k_embd1<<<SB * SS / 8, 256>>>(tok, tt, Ww, Wt, Wa, Wd, bd, out1);
    k_fill <<<dim3(SS, SB), 256>>>(tt, Wrel, out2);
}